// round 7
// baseline (speedup 1.0000x reference)
#include <cuda_runtime.h>
#include <cuda_bf16.h>
#include <cstdint>

// out[n,R,C,co] = active[n,R/14,C/14] * (bias[co] + sum_{dy,dx,ci} x[n,R+dy,C+dx,ci]*k[dy,dx,ci,co])
// valid 3x3 conv 506x506 -> 504x504, gated per 14x14 tile by mask-block max > 0.5
//
// mma.sync bf16 (fp32 = hi+lo bf16, 3 products AhBh+AhBl+AlBh), persistent CTAs.
// Tile 16x24, 6 warps, warp = 4 cols x 16 rows x 32 co; 2 CTAs/SM for overlap.
// A-fragments loaded once per (dy,h) and reused across the 3 dx taps.

#define N_IMG 8
#define H_IN  506
#define W_IN  506
#define H_OUT 504
#define W_OUT 504
#define NBH   36
#define NBW   36

#define RT_CNT 32                    // 16-row tiles (last partial rows guarded)
#define CT_CNT 21                    // 24-col tiles: 21*24 = 504 exact
#define N_TILES (N_IMG * RT_CNT * CT_CNT)   // 5376
#define GRID_CONV 296

#define XROWP 27                     // pixel-column pitch (27*9 = 243 ≡ 3 mod 8)
#define PIXB  144                    // 64B hi(ci0-31) + 64B lo + 16 pad
#define XS_BYTES (18 * XROWP * PIXB) // 69984
#define WROWB 80                     // 64B ci + 16 pad (5 chunks, odd)
#define WSPLIT (9 * 32 * WROWB)      // 23040
#define WS_BYTES (2 * WSPLIT)        // 46080
#define SMEM_BYTES (XS_BYTES + WS_BYTES)   // 116064  (2 CTAs = 226.7KB <= 228KB)

__device__ float g_active[N_IMG * NBH * NBW];

// ------------------------- helpers ------------------------------------------
__device__ __forceinline__ uint32_t smem_u32(const void* p) {
    uint32_t a;
    asm("{ .reg .u64 t; cvta.to.shared.u64 t, %1; cvt.u32.u64 %0, t; }"
        : "=r"(a) : "l"(p));
    return a;
}
__device__ __forceinline__ void sts64(uint32_t a, uint64_t v) {
    asm volatile("st.shared.b64 [%0], %1;" :: "r"(a), "l"(v) : "memory");
}
__device__ __forceinline__ void sts128(uint32_t a, uint32_t r0, uint32_t r1,
                                       uint32_t r2, uint32_t r3) {
    asm volatile("st.shared.v4.b32 [%0], {%1,%2,%3,%4};"
                 :: "r"(a), "r"(r0), "r"(r1), "r"(r2), "r"(r3) : "memory");
}
__device__ __forceinline__ void ldsm4(uint32_t* r, uint32_t addr) {
    asm volatile("ldmatrix.sync.aligned.m8n8.x4.shared.b16 {%0,%1,%2,%3}, [%4];"
                 : "=r"(r[0]), "=r"(r[1]), "=r"(r[2]), "=r"(r[3]) : "r"(addr));
}
__device__ __forceinline__ void mma4(float* d, const uint32_t* a, const uint32_t* b) {
    asm volatile(
        "mma.sync.aligned.m16n8k16.row.col.f32.bf16.bf16.f32 "
        "{%0,%1,%2,%3},{%4,%5,%6,%7},{%8,%9},{%0,%1,%2,%3};"
        : "+f"(d[0]), "+f"(d[1]), "+f"(d[2]), "+f"(d[3])
        : "r"(a[0]), "r"(a[1]), "r"(a[2]), "r"(a[3]), "r"(b[0]), "r"(b[1]));
}
__device__ __forceinline__ unsigned short bf_hi(float f) {
    return __bfloat16_as_ushort(__float2bfloat16_rn(f));
}

// ---------------- kernel 1: mask block max -> active flag -------------------
__global__ void __launch_bounds__(256) mask_kernel(const float* __restrict__ mask) {
    __shared__ float red[256];
    int b = blockIdx.x;
    int n   = b / (NBH * NBW);
    int rem = b % (NBH * NBW);
    int bi = rem / NBW, bj = rem % NBW;
    int tid = threadIdx.x;
    int rr = tid >> 4, cc = tid & 15;
    red[tid] = mask[(n * H_IN + bi * 14 + rr) * W_IN + bj * 14 + cc];
    __syncthreads();
    #pragma unroll
    for (int s = 128; s > 0; s >>= 1) {
        if (tid < s) red[tid] = fmaxf(red[tid], red[tid + s]);
        __syncthreads();
    }
    if (tid == 0) g_active[b] = (red[0] > 0.5f) ? 1.0f : 0.0f;
}

// ---------------- kernel 2: persistent conv via mma.sync --------------------
__global__ void __launch_bounds__(192, 2) conv_mma_kernel(
    const float* __restrict__ x,
    const float* __restrict__ kern,
    const float* __restrict__ bias,
    float* __restrict__ out)
{
    extern __shared__ char smem[];
    const uint32_t xs = smem_u32(smem);
    const uint32_t ws = xs + XS_BYTES;
    const int tid = threadIdx.x;
    const int wid = tid >> 5;
    const int lid = tid & 31;

    // ---- stage weights once: kern[tap][ci][co] -> ws[split][tap][co][ci bf16] ----
    for (int j = tid; j < 2304; j += 192) {
        int ciq = j & 7;
        int co  = (j >> 3) & 31;
        int tap = j >> 8;
        int ci  = ciq * 4;
        const float* kp = kern + (tap * 32 + ci) * 32 + co;
        float f0 = kp[0], f1 = kp[32], f2 = kp[64], f3 = kp[96];
        unsigned short h0 = bf_hi(f0), h1 = bf_hi(f1), h2 = bf_hi(f2), h3 = bf_hi(f3);
        unsigned short l0 = bf_hi(f0 - __bfloat162float(__ushort_as_bfloat16(h0)));
        unsigned short l1 = bf_hi(f1 - __bfloat162float(__ushort_as_bfloat16(h1)));
        unsigned short l2 = bf_hi(f2 - __bfloat162float(__ushort_as_bfloat16(h2)));
        unsigned short l3 = bf_hi(f3 - __bfloat162float(__ushort_as_bfloat16(h3)));
        uint64_t hi64 = (uint64_t)h0 | ((uint64_t)h1 << 16)
                      | ((uint64_t)h2 << 32) | ((uint64_t)h3 << 48);
        uint64_t lo64 = (uint64_t)l0 | ((uint64_t)l1 << 16)
                      | ((uint64_t)l2 << 32) | ((uint64_t)l3 << 48);
        uint32_t a = ws + (uint32_t)((tap * 32 + co) * WROWB + ciq * 8);
        sts64(a, hi64);
        sts64(a + WSPLIT, lo64);
    }

    // per-lane ldmatrix base addresses
    const int cw = wid * 4;
    const uint32_t baseA = xs + (uint32_t)
        (((((lid & 7) + 8 * ((lid >> 3) & 1)) * XROWP) + cw) * PIXB + (lid >> 4) * 16);
    const uint32_t baseB = ws + (uint32_t)
        ((((lid & 7) + ((lid >> 4) << 3)) * WROWB) + ((lid >> 3) & 1) * 16);

    // bias fragment (invariant)
    const int n2 = (lid & 3) * 2;
    float2 bv[4];
    #pragma unroll
    for (int nb = 0; nb < 4; nb++)
        bv[nb] = *(const float2*)(bias + nb * 8 + n2);

    for (int t = blockIdx.x; t < N_TILES; t += GRID_CONV) {
        const int n   = t / (RT_CNT * CT_CNT);
        const int rem = t % (RT_CNT * CT_CNT);
        const int R0 = (rem / CT_CNT) * 16;
        const int C0 = (rem % CT_CNT) * 24;

        __syncthreads();   // previous iteration's readers done before overwrite

        // ---- stage x: 18 rows x 26 cols x 32 ci, hi/lo bf16 (oct-outer) ----
        for (int j = tid; j < 1872; j += 192) {
            int oct = j / 468;                 // 8-ci group
            int p   = j - oct * 468;
            int ir = p / 26, ic = p - ir * 26;
            int gr = R0 + ir; if (gr > H_IN - 1) gr = H_IN - 1;
            int gc = C0 + ic;                  // <= 504+25 = 529? no: C0<=480, ic<=25 -> 505 ok
            const float4* gp = (const float4*)
                (x + (((size_t)n * H_IN + gr) * W_IN + gc) * 32 + oct * 8);
            float4 va = gp[0], vb = gp[1];
            float fv[8] = {va.x, va.y, va.z, va.w, vb.x, vb.y, vb.z, vb.w};
            uint32_t hi[4], lo[4];
            #pragma unroll
            for (int q = 0; q < 4; q++) {
                float f0 = fv[2 * q], f1 = fv[2 * q + 1];
                __nv_bfloat162 h = __floats2bfloat162_rn(f0, f1);
                float r0 = f0 - __bfloat162float(h.x);
                float r1 = f1 - __bfloat162float(h.y);
                __nv_bfloat162 lw = __floats2bfloat162_rn(r0, r1);
                hi[q] = *reinterpret_cast<uint32_t*>(&h);
                lo[q] = *reinterpret_cast<uint32_t*>(&lw);
            }
            uint32_t a = xs + (uint32_t)((ir * XROWP + ic) * PIXB + oct * 16);
            sts128(a,      hi[0], hi[1], hi[2], hi[3]);
            sts128(a + 64, lo[0], lo[1], lo[2], lo[3]);
        }
        __syncthreads();

        // ---- main loop: dy x h, A-frags shared across dx ----
        float d[4][4][4];
        #pragma unroll
        for (int f = 0; f < 4; f++)
            #pragma unroll
            for (int nb = 0; nb < 4; nb++)
                #pragma unroll
                for (int e = 0; e < 4; e++) d[f][nb][e] = 0.0f;

        #pragma unroll 1
        for (int dy = 0; dy < 3; dy++) {
            #pragma unroll 1
            for (int h = 0; h < 2; h++) {
                uint32_t Ah[24], Al[24], Bh[8], Bl[8];
                const uint32_t ao = baseA + (uint32_t)(dy * XROWP * PIXB + h * 32);
                #pragma unroll
                for (int j = 0; j < 6; j++) {
                    ldsm4(Ah + 4 * j, ao + j * PIXB);
                    ldsm4(Al + 4 * j, ao + j * PIXB + 64);
                }
                #pragma unroll
                for (int dx = 0; dx < 3; dx++) {
                    const uint32_t bo = baseB
                        + (uint32_t)((dy * 3 + dx) * (32 * WROWB) + h * 32);
                    ldsm4(Bh,     bo);
                    ldsm4(Bh + 4, bo + 16 * WROWB);
                    ldsm4(Bl,     bo + WSPLIT);
                    ldsm4(Bl + 4, bo + WSPLIT + 16 * WROWB);
                    #pragma unroll
                    for (int f = 0; f < 4; f++)
                        #pragma unroll
                        for (int nb = 0; nb < 4; nb++)
                            mma4(d[f][nb], Ah + 4 * (f + dx), Bh + 2 * nb);
                    #pragma unroll
                    for (int f = 0; f < 4; f++)
                        #pragma unroll
                        for (int nb = 0; nb < 4; nb++)
                            mma4(d[f][nb], Ah + 4 * (f + dx), Bl + 2 * nb);
                    #pragma unroll
                    for (int f = 0; f < 4; f++)
                        #pragma unroll
                        for (int nb = 0; nb < 4; nb++)
                            mma4(d[f][nb], Al + 4 * (f + dx), Bh + 2 * nb);
                }
            }
        }

        // ---- epilogue (C always < 504 since 21*24 = 504 exact) ----
        const int r0 = lid >> 2;
        const int R1 = R0 + r0;               // <= 503 always
        const int R2 = R1 + 8;
        const bool r2ok = (R2 < H_OUT);
        const int R2c = r2ok ? R2 : H_OUT - 1;
        const float* act1 = g_active + (n * NBH + R1 / 14) * NBW;
        const float* act2 = g_active + (n * NBH + R2c / 14) * NBW;

        #pragma unroll
        for (int f = 0; f < 4; f++) {
            const int C = C0 + cw + f;
            const int cb = C / 14;
            float fg1 = act1[cb];
            float* o1 = out + (((size_t)n * H_OUT + R1) * W_OUT + C) * 32 + n2;
            #pragma unroll
            for (int nb = 0; nb < 4; nb++) {
                float2 v;
                v.x = (d[f][nb][0] + bv[nb].x) * fg1;
                v.y = (d[f][nb][1] + bv[nb].y) * fg1;
                *(float2*)(o1 + nb * 8) = v;
            }
            if (r2ok) {
                float fg2 = act2[cb];
                float* o2 = out + (((size_t)n * H_OUT + R2) * W_OUT + C) * 32 + n2;
                #pragma unroll
                for (int nb = 0; nb < 4; nb++) {
                    float2 v;
                    v.x = (d[f][nb][2] + bv[nb].x) * fg2;
                    v.y = (d[f][nb][3] + bv[nb].y) * fg2;
                    *(float2*)(o2 + nb * 8) = v;
                }
            }
        }
    }
}

// ---------------------------------------------------------------------------
extern "C" void kernel_launch(void* const* d_in, const int* in_sizes, int n_in,
                              void* d_out, int out_size)
{
    const float* x    = (const float*)d_in[0];
    const float* mask = (const float*)d_in[1];
    const float* kern = (const float*)d_in[2];
    const float* bias = (const float*)d_in[3];
    float* out = (float*)d_out;
    (void)in_sizes; (void)n_in; (void)out_size;

    cudaFuncSetAttribute(conv_mma_kernel,
                         cudaFuncAttributeMaxDynamicSharedMemorySize, SMEM_BYTES);

    mask_kernel<<<N_IMG * NBH * NBW, 256>>>(mask);
    conv_mma_kernel<<<GRID_CONV, 192, SMEM_BYTES>>>(x, kern, bias, out);
}

// round 8
// speedup vs baseline: 1.4420x; 1.4420x over previous
#include <cuda_runtime.h>
#include <cuda_bf16.h>
#include <cstdint>

// out[n,R,C,co] = active[n,R/14,C/14] * (bias[co] + sum_{dy,dx,ci} x[n,R+dy,C+dx,ci]*k[dy,dx,ci,co])
// valid 3x3 conv 506x506 -> 504x504, gated per 14x14 tile by mask-block max > 0.5
//
// mma.sync bf16 (fp32 = hi+lo bf16, 3 products AhBh+AhBl+AlBh), persistent CTAs.
// Tile 16x24, 6 warps, warp = 4 cols x 16 rows x 32 co; 2 CTAs/SM (smem 111.5KB).
// A-fragments loaded once per (dy,h), reused across the 3 dx taps.
// Weights hi/lo interleaved in one 144B row to fit the 2-CTA smem budget.

#define N_IMG 8
#define H_IN  506
#define W_IN  506
#define H_OUT 504
#define W_OUT 504
#define NBH   36
#define NBW   36

#define RT_CNT 32                    // 16-row tiles (last rows guarded)
#define CT_CNT 21                    // 24-col tiles: 21*24 = 504 exact
#define N_TILES (N_IMG * RT_CNT * CT_CNT)   // 5376
#define GRID_CONV 296

#define XROWP 27                     // pixel-column pitch
#define PIXB  144                    // 64B hi(ci0-31) + 64B lo + 16 pad (9x16B, odd)
#define XS_BYTES (18 * XROWP * PIXB) // 69984
#define WROWB 144                    // 64B hi ci + 64B lo ci + 16 pad (odd 16B pitch)
#define WS_BYTES (9 * 32 * WROWB)    // 41472
#define SMEM_BYTES (XS_BYTES + WS_BYTES)   // 111456  -> 2 CTAs/SM

__device__ float g_active[N_IMG * NBH * NBW];

// ------------------------- helpers ------------------------------------------
__device__ __forceinline__ uint32_t smem_u32(const void* p) {
    uint32_t a;
    asm("{ .reg .u64 t; cvta.to.shared.u64 t, %1; cvt.u32.u64 %0, t; }"
        : "=r"(a) : "l"(p));
    return a;
}
__device__ __forceinline__ void sts64(uint32_t a, uint64_t v) {
    asm volatile("st.shared.b64 [%0], %1;" :: "r"(a), "l"(v) : "memory");
}
__device__ __forceinline__ void sts128(uint32_t a, uint32_t r0, uint32_t r1,
                                       uint32_t r2, uint32_t r3) {
    asm volatile("st.shared.v4.b32 [%0], {%1,%2,%3,%4};"
                 :: "r"(a), "r"(r0), "r"(r1), "r"(r2), "r"(r3) : "memory");
}
__device__ __forceinline__ void ldsm4(uint32_t* r, uint32_t addr) {
    asm volatile("ldmatrix.sync.aligned.m8n8.x4.shared.b16 {%0,%1,%2,%3}, [%4];"
                 : "=r"(r[0]), "=r"(r[1]), "=r"(r[2]), "=r"(r[3]) : "r"(addr));
}
__device__ __forceinline__ void mma4(float* d, const uint32_t* a, const uint32_t* b) {
    asm volatile(
        "mma.sync.aligned.m16n8k16.row.col.f32.bf16.bf16.f32 "
        "{%0,%1,%2,%3},{%4,%5,%6,%7},{%8,%9},{%0,%1,%2,%3};"
        : "+f"(d[0]), "+f"(d[1]), "+f"(d[2]), "+f"(d[3])
        : "r"(a[0]), "r"(a[1]), "r"(a[2]), "r"(a[3]), "r"(b[0]), "r"(b[1]));
}
__device__ __forceinline__ unsigned short bf_hi(float f) {
    return __bfloat16_as_ushort(__float2bfloat16_rn(f));
}

// ---------------- kernel 1: mask block max -> active flag -------------------
__global__ void __launch_bounds__(256) mask_kernel(const float* __restrict__ mask) {
    __shared__ float red[256];
    int b = blockIdx.x;
    int n   = b / (NBH * NBW);
    int rem = b % (NBH * NBW);
    int bi = rem / NBW, bj = rem % NBW;
    int tid = threadIdx.x;
    int rr = tid >> 4, cc = tid & 15;
    red[tid] = mask[(n * H_IN + bi * 14 + rr) * W_IN + bj * 14 + cc];
    __syncthreads();
    #pragma unroll
    for (int s = 128; s > 0; s >>= 1) {
        if (tid < s) red[tid] = fmaxf(red[tid], red[tid + s]);
        __syncthreads();
    }
    if (tid == 0) g_active[b] = (red[0] > 0.5f) ? 1.0f : 0.0f;
}

// ---------------- kernel 2: persistent conv via mma.sync --------------------
__global__ void __launch_bounds__(192, 2) conv_mma_kernel(
    const float* __restrict__ x,
    const float* __restrict__ kern,
    const float* __restrict__ bias,
    float* __restrict__ out)
{
    extern __shared__ char smem[];
    const uint32_t xs = smem_u32(smem);
    const uint32_t ws = xs + XS_BYTES;
    const int tid = threadIdx.x;
    const int wid = tid >> 5;
    const int lid = tid & 31;

    // ---- stage weights once: kern[tap][ci][co] -> ws[tap][co][hi ci | lo ci] ----
    for (int j = tid; j < 2304; j += 192) {
        int ciq = j & 7;
        int co  = (j >> 3) & 31;
        int tap = j >> 8;
        int ci  = ciq * 4;
        const float* kp = kern + (tap * 32 + ci) * 32 + co;
        float f0 = kp[0], f1 = kp[32], f2 = kp[64], f3 = kp[96];
        unsigned short h0 = bf_hi(f0), h1 = bf_hi(f1), h2 = bf_hi(f2), h3 = bf_hi(f3);
        unsigned short l0 = bf_hi(f0 - __bfloat162float(__ushort_as_bfloat16(h0)));
        unsigned short l1 = bf_hi(f1 - __bfloat162float(__ushort_as_bfloat16(h1)));
        unsigned short l2 = bf_hi(f2 - __bfloat162float(__ushort_as_bfloat16(h2)));
        unsigned short l3 = bf_hi(f3 - __bfloat162float(__ushort_as_bfloat16(h3)));
        uint64_t hi64 = (uint64_t)h0 | ((uint64_t)h1 << 16)
                      | ((uint64_t)h2 << 32) | ((uint64_t)h3 << 48);
        uint64_t lo64 = (uint64_t)l0 | ((uint64_t)l1 << 16)
                      | ((uint64_t)l2 << 32) | ((uint64_t)l3 << 48);
        uint32_t a = ws + (uint32_t)((tap * 32 + co) * WROWB + ciq * 8);
        sts64(a, hi64);
        sts64(a + 64, lo64);
    }

    // per-lane ldmatrix base addresses
    const int cw = wid * 4;
    const uint32_t baseA = xs + (uint32_t)
        (((((lid & 7) + 8 * ((lid >> 3) & 1)) * XROWP) + cw) * PIXB + (lid >> 4) * 16);
    const uint32_t baseB = ws + (uint32_t)
        ((((lid & 7) + ((lid >> 4) << 3)) * WROWB) + ((lid >> 3) & 1) * 16);

    // bias fragment (invariant)
    const int n2 = (lid & 3) * 2;
    float2 bv[4];
    #pragma unroll
    for (int nb = 0; nb < 4; nb++)
        bv[nb] = *(const float2*)(bias + nb * 8 + n2);

    for (int t = blockIdx.x; t < N_TILES; t += GRID_CONV) {
        const int n   = t / (RT_CNT * CT_CNT);
        const int rem = t % (RT_CNT * CT_CNT);
        const int R0 = (rem / CT_CNT) * 16;
        const int C0 = (rem % CT_CNT) * 24;

        __syncthreads();   // previous iteration's readers done before overwrite

        // ---- stage x: 18 rows x 26 cols x 32 ci, hi/lo bf16 (oct-outer) ----
        for (int j = tid; j < 1872; j += 192) {
            int oct = j / 468;                 // 8-ci group
            int p   = j - oct * 468;
            int ir = p / 26, ic = p - ir * 26;
            int gr = R0 + ir; if (gr > H_IN - 1) gr = H_IN - 1;
            int gc = C0 + ic;                  // C0<=480, ic<=25 -> gc<=505, in range
            const float4* gp = (const float4*)
                (x + (((size_t)n * H_IN + gr) * W_IN + gc) * 32 + oct * 8);
            float4 va = gp[0], vb = gp[1];
            float fv[8] = {va.x, va.y, va.z, va.w, vb.x, vb.y, vb.z, vb.w};
            uint32_t hi[4], lo[4];
            #pragma unroll
            for (int q = 0; q < 4; q++) {
                float f0 = fv[2 * q], f1 = fv[2 * q + 1];
                __nv_bfloat162 h = __floats2bfloat162_rn(f0, f1);
                float r0 = f0 - __bfloat162float(h.x);
                float r1 = f1 - __bfloat162float(h.y);
                __nv_bfloat162 lw = __floats2bfloat162_rn(r0, r1);
                hi[q] = *reinterpret_cast<uint32_t*>(&h);
                lo[q] = *reinterpret_cast<uint32_t*>(&lw);
            }
            uint32_t a = xs + (uint32_t)((ir * XROWP + ic) * PIXB + oct * 16);
            sts128(a,      hi[0], hi[1], hi[2], hi[3]);
            sts128(a + 64, lo[0], lo[1], lo[2], lo[3]);
        }
        __syncthreads();

        // ---- main loop: dy x h, A-frags shared across dx ----
        float d[4][4][4];
        #pragma unroll
        for (int f = 0; f < 4; f++)
            #pragma unroll
            for (int nb = 0; nb < 4; nb++)
                #pragma unroll
                for (int e = 0; e < 4; e++) d[f][nb][e] = 0.0f;

        #pragma unroll 1
        for (int dy = 0; dy < 3; dy++) {
            #pragma unroll 1
            for (int h = 0; h < 2; h++) {
                uint32_t Ah[24], Al[24], Bh[8], Bl[8];
                const uint32_t ao = baseA + (uint32_t)(dy * XROWP * PIXB + h * 32);
                #pragma unroll
                for (int j = 0; j < 6; j++) {
                    ldsm4(Ah + 4 * j, ao + j * PIXB);
                    ldsm4(Al + 4 * j, ao + j * PIXB + 64);
                }
                #pragma unroll
                for (int dx = 0; dx < 3; dx++) {
                    const uint32_t bo = baseB
                        + (uint32_t)((dy * 3 + dx) * (32 * WROWB) + h * 32);
                    ldsm4(Bh,     bo);
                    ldsm4(Bh + 4, bo + 16 * WROWB);
                    ldsm4(Bl,     bo + 64);
                    ldsm4(Bl + 4, bo + 64 + 16 * WROWB);
                    #pragma unroll
                    for (int f = 0; f < 4; f++)
                        #pragma unroll
                        for (int nb = 0; nb < 4; nb++)
                            mma4(d[f][nb], Ah + 4 * (f + dx), Bh + 2 * nb);
                    #pragma unroll
                    for (int f = 0; f < 4; f++)
                        #pragma unroll
                        for (int nb = 0; nb < 4; nb++)
                            mma4(d[f][nb], Ah + 4 * (f + dx), Bl + 2 * nb);
                    #pragma unroll
                    for (int f = 0; f < 4; f++)
                        #pragma unroll
                        for (int nb = 0; nb < 4; nb++)
                            mma4(d[f][nb], Al + 4 * (f + dx), Bh + 2 * nb);
                }
            }
        }

        // ---- epilogue (C always < 504 since 21*24 = 504 exact) ----
        const int r0 = lid >> 2;
        const int R1 = R0 + r0;               // <= 503 always
        const int R2 = R1 + 8;
        const bool r2ok = (R2 < H_OUT);
        const int R2c = r2ok ? R2 : H_OUT - 1;
        const float* act1 = g_active + (n * NBH + R1 / 14) * NBW;
        const float* act2 = g_active + (n * NBH + R2c / 14) * NBW;

        #pragma unroll
        for (int f = 0; f < 4; f++) {
            const int C = C0 + cw + f;
            const int cb = C / 14;
            float fg1 = act1[cb];
            float* o1 = out + (((size_t)n * H_OUT + R1) * W_OUT + C) * 32 + n2;
            #pragma unroll
            for (int nb = 0; nb < 4; nb++) {
                float2 v;
                v.x = (d[f][nb][0] + bv[nb].x) * fg1;
                v.y = (d[f][nb][1] + bv[nb].y) * fg1;
                *(float2*)(o1 + nb * 8) = v;
            }
            if (r2ok) {
                float fg2 = act2[cb];
                float* o2 = out + (((size_t)n * H_OUT + R2) * W_OUT + C) * 32 + n2;
                #pragma unroll
                for (int nb = 0; nb < 4; nb++) {
                    float2 v;
                    v.x = (d[f][nb][2] + bv[nb].x) * fg2;
                    v.y = (d[f][nb][3] + bv[nb].y) * fg2;
                    *(float2*)(o2 + nb * 8) = v;
                }
            }
        }
    }
}

// ---------------------------------------------------------------------------
extern "C" void kernel_launch(void* const* d_in, const int* in_sizes, int n_in,
                              void* d_out, int out_size)
{
    const float* x    = (const float*)d_in[0];
    const float* mask = (const float*)d_in[1];
    const float* kern = (const float*)d_in[2];
    const float* bias = (const float*)d_in[3];
    float* out = (float*)d_out;
    (void)in_sizes; (void)n_in; (void)out_size;

    cudaFuncSetAttribute(conv_mma_kernel,
                         cudaFuncAttributeMaxDynamicSharedMemorySize, SMEM_BYTES);

    mask_kernel<<<N_IMG * NBH * NBW, 256>>>(mask);
    conv_mma_kernel<<<GRID_CONV, 192, SMEM_BYTES>>>(x, kern, bias, out);
}